// round 8
// baseline (speedup 1.0000x reference)
#include <cuda_runtime.h>
#include <cstddef>

#define BATCH_N 16384
#define SEQ_N   512
#define HID_N   5
#define FLAT_N  2560        // SEQ_N*HID_N
#define TPB     384         // 12 warps = 3 warps/SMSP
#define EPB     120         // elements per block: 12 warps x 10 groups

// Collapsed linear head: Weff = W2 @ W1 (1 x 2560), beff = W2@b1 + b2
__device__ float g_Weff[FLAT_N];
__device__ float g_beff;

// ---------------------------------------------------------------------------
// Kernel 1: collapse the two linear layers (no nonlinearity between them).
// ---------------------------------------------------------------------------
__global__ void weff_kernel(const float* __restrict__ W1,
                            const float* __restrict__ b1,
                            const float* __restrict__ W2,
                            const float* __restrict__ b2)
{
    int j = blockIdx.x * blockDim.x + threadIdx.x;
    if (j < FLAT_N) {
        float acc = 0.0f;
        #pragma unroll 8
        for (int k = 0; k < 512; ++k)
            acc = fmaf(W2[k], W1[(size_t)k * FLAT_N + j], acc);
        g_Weff[j] = acc;
    }
    if (j == 0) {
        float acc = b2[0];
        for (int k = 0; k < 512; ++k)
            acc = fmaf(W2[k], b1[k], acc);
        g_beff = acc;
    }
}

// ---------------------------------------------------------------------------
// Packed f32x2 + fast-activation primitives
// ---------------------------------------------------------------------------
typedef unsigned long long u64;

__device__ __forceinline__ u64 pack2(float lo, float hi) {
    u64 r; asm("mov.b64 %0, {%1, %2};" : "=l"(r) : "f"(lo), "f"(hi)); return r;
}
__device__ __forceinline__ void unpack2(u64 v, float& lo, float& hi) {
    asm("mov.b64 {%0, %1}, %2;" : "=f"(lo), "=f"(hi) : "l"(v));
}
__device__ __forceinline__ u64 fma2(u64 a, u64 b, u64 c) {
    u64 d; asm("fma.rn.f32x2 %0, %1, %2, %3;" : "=l"(d) : "l"(a), "l"(b), "l"(c)); return d;
}
__device__ __forceinline__ u64 mul2(u64 a, u64 b) {
    u64 d; asm("mul.rn.f32x2 %0, %1, %2;" : "=l"(d) : "l"(a), "l"(b)); return d;
}
__device__ __forceinline__ float tanh_fast(float x) {
    float y; asm("tanh.approx.f32 %0, %1;" : "=f"(y) : "f"(x)); return y;
}
__device__ __forceinline__ float sig_fast(float x) {
    return fmaf(0.5f, tanh_fast(0.5f * x), 0.5f);
}

// ---------------------------------------------------------------------------
// Kernel 2: THREE threads per batch element (3-lane groups; lanes 30,31 idle).
//   role r owns unit slots {2r, 2r+1}; role 2's slot 1 is a zero-weight dummy
//   (its h is identically 0 and is never consumed).
// Each thread: 4 gate-pair f32x2 chains per layer (pairs: (i,f),(g,o) x 2 units).
// h exchange: 5 computed-lane shfls per layer. No column permutation.
// Layer-1 weights (44 u64) register-resident. Layer-0 via LDS.128.
// ---------------------------------------------------------------------------
__global__ void __launch_bounds__(TPB, 1)
lstm_fused_kernel(const float* __restrict__ x,
                  const float* __restrict__ Wih0, const float* __restrict__ Whh0,
                  const float* __restrict__ bih0, const float* __restrict__ bhh0,
                  const float* __restrict__ Wih1, const float* __restrict__ Whh1,
                  const float* __restrict__ bih1, const float* __restrict__ bhh1,
                  float* __restrict__ out)
{
    // [role][pair][slot]; L0 slots: B, Wih, Whh c0..c4, pad (8 u64 = 64B)
    //                     L1 slots: B, Wih1 c0..c4, Whh1 c0..c4, pad (12 u64)
    __shared__ __align__(16) u64 sL0[3][4][8];
    __shared__ __align__(16) u64 sL1[3][4][12];
    __shared__ __align__(16) u64 sWeffP[3][SEQ_N];

    const int t = threadIdx.x;

    // ---- build role-specialized packed weight tables (12 builder threads) ----
    if (t < 12) {
        const int r = t >> 2, p = t & 3;
        const int u = 2 * r + (p >> 1);            // unit slot id
        const bool dummy = (u >= HID_N);
        const int uc = dummy ? 0 : u;
        const float m = dummy ? 0.0f : 1.0f;
        int rowA, rowB;
        if ((p & 1) == 0) { rowA = uc;      rowB = 5 + uc;  }   // (i_u, f_u)
        else              { rowA = 10 + uc; rowB = 15 + uc; }   // (g_u, o_u)

        sL0[r][p][0] = pack2(m * (bih0[rowA] + bhh0[rowA]), m * (bih0[rowB] + bhh0[rowB]));
        sL0[r][p][1] = pack2(m * Wih0[rowA], m * Wih0[rowB]);
        sL1[r][p][0] = pack2(m * (bih1[rowA] + bhh1[rowA]), m * (bih1[rowB] + bhh1[rowB]));
        #pragma unroll
        for (int k = 0; k < HID_N; ++k) {
            sL0[r][p][2 + k] = pack2(m * Whh0[rowA * HID_N + k], m * Whh0[rowB * HID_N + k]);
            sL1[r][p][1 + k] = pack2(m * Wih1[rowA * HID_N + k], m * Wih1[rowB * HID_N + k]);
            sL1[r][p][6 + k] = pack2(m * Whh1[rowA * HID_N + k], m * Whh1[rowB * HID_N + k]);
        }
        sL0[r][p][7]  = 0ull;
        sL1[r][p][11] = 0ull;
    }
    for (int s = t; s < SEQ_N; s += TPB) {
        sWeffP[0][s] = pack2(g_Weff[5 * s + 0], g_Weff[5 * s + 1]);
        sWeffP[1][s] = pack2(g_Weff[5 * s + 2], g_Weff[5 * s + 3]);
        sWeffP[2][s] = pack2(g_Weff[5 * s + 4], 0.0f);
    }
    __syncthreads();

    const int lane  = t & 31;
    const int warp  = t >> 5;
    const int group = lane / 3;                 // 0..9 real, 10 = idle lanes 30,31
    const int role  = lane - group * 3;         // 0..2
    const int baseL = group * 3;

    const int  e_raw = blockIdx.x * EPB + warp * 10 + group;
    const bool valid = (group < 10) && (e_raw < BATCH_N);
    const int  e     = valid ? e_raw : 0;

    const float4* __restrict__ xr4 = (const float4*)(x + (size_t)e * SEQ_N);
    const u64 (*__restrict__ L0)[8] = sL0[role];
    const u64*  __restrict__ WfP    = sWeffP[role];

    // ---- hoist layer-1 weights into registers (44 u64 = 88 regs) ----
    u64 w1[4][11];
    {
        const u64 (*__restrict__ L1s)[12] = sL1[role];
        #pragma unroll
        for (int p = 0; p < 4; ++p)
            #pragma unroll
            for (int k = 0; k < 11; ++k)
                w1[p][k] = L1s[p][k];
    }

    const u64 HALF2 = pack2(0.5f, 0.5f);

    u64 h0v[HID_N], h1v[HID_N];                 // broadcast-packed full h vectors
    float c0[2], c1[2];                         // own 2 unit-slots' cell state
    #pragma unroll
    for (int k = 0; k < HID_N; ++k) { h0v[k] = 0ull; h1v[k] = 0ull; }
    c0[0] = c0[1] = c1[0] = c1[1] = 0.f;

    u64 acc2 = 0ull;

    #pragma unroll 1
    for (int s4 = 0; s4 < SEQ_N / 4; ++s4) {
        const float4 xq = __ldg(&xr4[s4]);

        #pragma unroll
        for (int su = 0; su < 4; ++su) {
            const int s = 4 * s4 + su;
            const float xin = (su == 0) ? xq.x : (su == 1) ? xq.y : (su == 2) ? xq.z : xq.w;
            const u64 xx = pack2(xin, xin);

            // ---- layer 0: 4 packed gate-pair chains (LDS.128) ----
            u64 ga[4];
            #pragma unroll
            for (int p = 0; p < 4; ++p) {
                u64 a = fma2(L0[p][1], xx, L0[p][0]);
                #pragma unroll
                for (int k = 0; k < HID_N; ++k)
                    a = fma2(L0[p][2 + k], h0v[k], a);
                ga[p] = a;
            }
            // ---- layer 0 activations (own 2 unit slots) ----
            float hu0, hu1;
            #pragma unroll
            for (int q = 0; q < 2; ++q) {
                float iv, fv, gv, ov, ig, fg;
                unpack2(mul2(ga[2 * q], HALF2), iv, fv);
                float ti = tanh_fast(iv), tf = tanh_fast(fv);
                unpack2(fma2(pack2(ti, tf), HALF2, HALF2), ig, fg);
                unpack2(ga[2 * q + 1], gv, ov);
                float gg = tanh_fast(gv);
                float og = sig_fast(ov);
                float c = fmaf(fg, c0[q], ig * gg);
                c0[q] = c;
                float h = og * tanh_fast(c);
                if (q == 0) hu0 = h; else hu1 = h;
            }
            // ---- exchange full h0: 5 computed-lane shfls ----
            {
                float a0 = __shfl_sync(0xffffffffu, hu0, baseL);
                float a1 = __shfl_sync(0xffffffffu, hu1, baseL);
                float a2 = __shfl_sync(0xffffffffu, hu0, baseL + 1);
                float a3 = __shfl_sync(0xffffffffu, hu1, baseL + 1);
                float a4 = __shfl_sync(0xffffffffu, hu0, baseL + 2);
                h0v[0] = pack2(a0, a0);
                h0v[1] = pack2(a1, a1);
                h0v[2] = pack2(a2, a2);
                h0v[3] = pack2(a3, a3);
                h0v[4] = pack2(a4, a4);
            }

            // ---- layer 1: 4 packed gate-pair chains (register weights) ----
            #pragma unroll
            for (int p = 0; p < 4; ++p) {
                u64 a = w1[p][0];
                #pragma unroll
                for (int k = 0; k < HID_N; ++k)
                    a = fma2(w1[p][1 + k], h0v[k], a);
                #pragma unroll
                for (int k = 0; k < HID_N; ++k)
                    a = fma2(w1[p][6 + k], h1v[k], a);
                ga[p] = a;
            }
            // ---- layer 1 activations ----
            #pragma unroll
            for (int q = 0; q < 2; ++q) {
                float iv, fv, gv, ov, ig, fg;
                unpack2(mul2(ga[2 * q], HALF2), iv, fv);
                float ti = tanh_fast(iv), tf = tanh_fast(fv);
                unpack2(fma2(pack2(ti, tf), HALF2, HALF2), ig, fg);
                unpack2(ga[2 * q + 1], gv, ov);
                float gg = tanh_fast(gv);
                float og = sig_fast(ov);
                float c = fmaf(fg, c1[q], ig * gg);
                c1[q] = c;
                float h = og * tanh_fast(c);
                if (q == 0) hu0 = h; else hu1 = h;
            }
            // ---- folded head: role-partitioned packed dot (r2: (W4,0)) ----
            acc2 = fma2(pack2(hu0, hu1), WfP[s], acc2);

            // ---- exchange full h1 ----
            {
                float a0 = __shfl_sync(0xffffffffu, hu0, baseL);
                float a1 = __shfl_sync(0xffffffffu, hu1, baseL);
                float a2 = __shfl_sync(0xffffffffu, hu0, baseL + 1);
                float a3 = __shfl_sync(0xffffffffu, hu1, baseL + 1);
                float a4 = __shfl_sync(0xffffffffu, hu0, baseL + 2);
                h1v[0] = pack2(a0, a0);
                h1v[1] = pack2(a1, a1);
                h1v[2] = pack2(a2, a2);
                h1v[3] = pack2(a3, a3);
                h1v[4] = pack2(a4, a4);
            }
        }
    }

    // ---- combine the 3 role partials; role 0 of each valid group writes ----
    float alo, ahi;
    unpack2(acc2, alo, ahi);
    float part = alo + ahi;
    float p0 = __shfl_sync(0xffffffffu, part, baseL);
    float p1 = __shfl_sync(0xffffffffu, part, baseL + 1);
    float p2 = __shfl_sync(0xffffffffu, part, baseL + 2);
    if (role == 0 && valid)
        out[e] = p0 + p1 + p2 + g_beff;
}

// ---------------------------------------------------------------------------
// Harness entry. Inputs in metadata order:
// x, Wih0, Whh0, bih0, bhh0, Wih1, Whh1, bih1, bhh1, W1, b1, W2, b2
// ---------------------------------------------------------------------------
extern "C" void kernel_launch(void* const* d_in, const int* in_sizes, int n_in,
                              void* d_out, int out_size)
{
    const float* x    = (const float*)d_in[0];
    const float* Wih0 = (const float*)d_in[1];
    const float* Whh0 = (const float*)d_in[2];
    const float* bih0 = (const float*)d_in[3];
    const float* bhh0 = (const float*)d_in[4];
    const float* Wih1 = (const float*)d_in[5];
    const float* Whh1 = (const float*)d_in[6];
    const float* bih1 = (const float*)d_in[7];
    const float* bhh1 = (const float*)d_in[8];
    const float* W1   = (const float*)d_in[9];
    const float* b1   = (const float*)d_in[10];
    const float* W2   = (const float*)d_in[11];
    const float* b2   = (const float*)d_in[12];
    float* out = (float*)d_out;

    weff_kernel<<<(FLAT_N + 511) / 512, 512>>>(W1, b1, W2, b2);

    // 3 threads/element, 384-thread blocks (12 warps = 3/SMSP), 120 elems/block
    const int nblocks = (BATCH_N + EPB - 1) / EPB;   // 137 <= 148 SMs, one wave
    lstm_fused_kernel<<<nblocks, TPB>>>(x, Wih0, Whh0, bih0, bhh0,
                                        Wih1, Whh1, bih1, bhh1, out);
}

// round 9
// speedup vs baseline: 1.3127x; 1.3127x over previous
#include <cuda_runtime.h>
#include <cstddef>

#define BATCH_N 16384
#define SEQ_N   512
#define HID_N   5
#define FLAT_N  2560        // SEQ_N*HID_N

// Collapsed linear head: Weff = W2 @ W1 (1 x 2560), beff = W2@b1 + b2
__device__ float g_Weff[FLAT_N];
__device__ float g_beff;

// ---------------------------------------------------------------------------
// Kernel 1: collapse the two linear layers (no nonlinearity between them).
// ---------------------------------------------------------------------------
__global__ void weff_kernel(const float* __restrict__ W1,
                            const float* __restrict__ b1,
                            const float* __restrict__ W2,
                            const float* __restrict__ b2)
{
    int j = blockIdx.x * blockDim.x + threadIdx.x;
    if (j < FLAT_N) {
        float acc = 0.0f;
        #pragma unroll 8
        for (int k = 0; k < 512; ++k)
            acc = fmaf(W2[k], W1[(size_t)k * FLAT_N + j], acc);
        g_Weff[j] = acc;
    }
    if (j == 0) {
        float acc = b2[0];
        for (int k = 0; k < 512; ++k)
            acc = fmaf(W2[k], b1[k], acc);
        g_beff = acc;
    }
}

// ---------------------------------------------------------------------------
// Packed f32x2 + fast-activation primitives
// ---------------------------------------------------------------------------
typedef unsigned long long u64;

__device__ __forceinline__ u64 pack2(float lo, float hi) {
    u64 r; asm("mov.b64 %0, {%1, %2};" : "=l"(r) : "f"(lo), "f"(hi)); return r;
}
__device__ __forceinline__ void unpack2(u64 v, float& lo, float& hi) {
    asm("mov.b64 {%0, %1}, %2;" : "=f"(lo), "=f"(hi) : "l"(v));
}
__device__ __forceinline__ u64 fma2(u64 a, u64 b, u64 c) {
    u64 d; asm("fma.rn.f32x2 %0, %1, %2, %3;" : "=l"(d) : "l"(a), "l"(b), "l"(c)); return d;
}
__device__ __forceinline__ u64 mul2(u64 a, u64 b) {
    u64 d; asm("mul.rn.f32x2 %0, %1, %2;" : "=l"(d) : "l"(a), "l"(b)); return d;
}
__device__ __forceinline__ float tanh_fast(float x) {
    float y; asm("tanh.approx.f32 %0, %1;" : "=f"(y) : "f"(x)); return y;
}
__device__ __forceinline__ float sig_fast(float x) {
    return fmaf(0.5f, tanh_fast(0.5f * x), 0.5f);
}

// ---------------------------------------------------------------------------
// Kernel 2: TWO threads per batch element (lanes 2k / 2k+1) — round-7 layout —
// PLUS cross-step software pipelining: layer-0 gate chains for step s+1 are
// issued right after the h0 exchange of step s, overlapping the layer-1
// chains + activations of step s (they are data-independent).
//   role 0 owns hidden units {0,1,2}; role 1 owns {2,3,4} (unit 2 duplicated).
// Layer-1 weights (66 u64) register-resident; layer-0 via LDS.128.
// ---------------------------------------------------------------------------
__global__ void __launch_bounds__(256)
lstm_fused_kernel(const float* __restrict__ x,
                  const float* __restrict__ Wih0, const float* __restrict__ Whh0,
                  const float* __restrict__ bih0, const float* __restrict__ bhh0,
                  const float* __restrict__ Wih1, const float* __restrict__ Whh1,
                  const float* __restrict__ bih1, const float* __restrict__ bhh1,
                  float* __restrict__ out)
{
    __shared__ __align__(16) u64 sL0[2][6][8];
    __shared__ __align__(16) u64 sL1[2][6][12];
    __shared__ __align__(16) u64 sWeffP[2][SEQ_N];
    __shared__ float sWeffS[2][SEQ_N];

    const int t = threadIdx.x;

    // ---- build role-specialized packed weight tables ----
    if (t < 12) {
        const int r = t / 6, p = t % 6;
        const int q = p >> 1;                       // unit slot 0..2
        const int j = (r == 0) ? q : q + 2;         // unit id: lo {0,1,2}, hi {2,3,4}
        int rowA, rowB;
        if ((p & 1) == 0) { rowA = j;      rowB = 5 + j;  }   // (i_j, f_j)
        else              { rowA = 10 + j; rowB = 15 + j; }   // (g_j, o_j)

        sL0[r][p][0] = pack2(bih0[rowA] + bhh0[rowA], bih0[rowB] + bhh0[rowB]);
        sL0[r][p][1] = pack2(Wih0[rowA], Wih0[rowB]);
        sL1[r][p][0] = pack2(bih1[rowA] + bhh1[rowA], bih1[rowB] + bhh1[rowB]);
        #pragma unroll
        for (int k = 0; k < HID_N; ++k) {
            const int c = (r == 0) ? k : (k + 2) % HID_N;   // column permutation
            sL0[r][p][2 + k] = pack2(Whh0[rowA * HID_N + c], Whh0[rowB * HID_N + c]);
            sL1[r][p][1 + k] = pack2(Wih1[rowA * HID_N + c], Wih1[rowB * HID_N + c]);
            sL1[r][p][6 + k] = pack2(Whh1[rowA * HID_N + c], Whh1[rowB * HID_N + c]);
        }
        sL0[r][p][7]  = 0ull;
        sL1[r][p][11] = 0ull;
    }
    for (int s = t; s < SEQ_N; s += blockDim.x) {
        sWeffP[0][s] = pack2(g_Weff[5 * s + 0], g_Weff[5 * s + 1]);
        sWeffP[1][s] = pack2(g_Weff[5 * s + 2], g_Weff[5 * s + 3]);
        sWeffS[0][s] = 0.0f;
        sWeffS[1][s] = g_Weff[5 * s + 4];
    }
    __syncthreads();

    const int gid = blockIdx.x * blockDim.x + t;
    const int e   = gid >> 1;          // batch element
    const int r   = gid & 1;           // role
    const float4* __restrict__ xr4 = (const float4*)(x + (size_t)e * SEQ_N);

    const u64 (*__restrict__ L0)[8] = sL0[r];
    const u64*   __restrict__ WfP   = sWeffP[r];
    const float* __restrict__ WfS   = sWeffS[r];

    // ---- hoist layer-1 weights into registers (66 u64 = 132 regs) ----
    u64 w1[6][11];
    {
        const u64 (*__restrict__ L1s)[12] = sL1[r];
        #pragma unroll
        for (int p = 0; p < 6; ++p)
            #pragma unroll
            for (int k = 0; k < 11; ++k)
                w1[p][k] = L1s[p][k];
    }

    const u64 HALF2 = pack2(0.5f, 0.5f);

    u64 h0v[HID_N], h1v[HID_N];
    float c0[3], c1[3];
    #pragma unroll
    for (int k = 0; k < HID_N; ++k) { h0v[k] = 0ull; h1v[k] = 0ull; }
    #pragma unroll
    for (int q = 0; q < 3; ++q) { c0[q] = 0.f; c1[q] = 0.f; }

    u64 acc2 = 0ull;
    float accS = 0.0f;

    // layer-0 gate chains, written as a reusable lambda (reads h0v by ref)
    auto l0_chains = [&](u64* ga, u64 xx) {
        #pragma unroll
        for (int p = 0; p < 6; ++p) {
            u64 a = fma2(L0[p][1], xx, L0[p][0]);
            #pragma unroll
            for (int k = 0; k < HID_N; ++k)
                a = fma2(L0[p][2 + k], h0v[k], a);
            ga[p] = a;
        }
    };

    // ---- prologue: layer-0 gates for step 0 (h0v == 0) ----
    float4 xq = __ldg(&xr4[0]);
    u64 ga0[6];
    l0_chains(ga0, pack2(xq.x, xq.x));

    #pragma unroll 1
    for (int s4 = 0; s4 < SEQ_N / 4; ++s4) {
        float4 xq_next;
        if (s4 + 1 < SEQ_N / 4) xq_next = __ldg(&xr4[s4 + 1]);
        else                    xq_next = make_float4(0.f, 0.f, 0.f, 0.f);

        #pragma unroll
        for (int su = 0; su < 4; ++su) {
            const int s = 4 * s4 + su;
            // x for step s+1 (dummy 0 past the end; result discarded)
            const float xn = (su == 0) ? xq.y : (su == 1) ? xq.z
                           : (su == 2) ? xq.w : xq_next.x;

            // ---- layer 0 activations for step s (from pipelined ga0) ----
            float hu[3];
            #pragma unroll
            for (int q = 0; q < 3; ++q) {
                float iv, fv, gv, ov, ig, fg;
                unpack2(mul2(ga0[2 * q], HALF2), iv, fv);
                float ti = tanh_fast(iv), tf = tanh_fast(fv);
                unpack2(fma2(pack2(ti, tf), HALF2, HALF2), ig, fg);
                unpack2(ga0[2 * q + 1], gv, ov);
                float gg = tanh_fast(gv);
                float og = sig_fast(ov);
                float c = fmaf(fg, c0[q], ig * gg);
                c0[q] = c;
                hu[q] = og * tanh_fast(c);
            }
            // ---- exchange h0: lo sends (h0,h1), hi sends (h3,h4) ----
            {
                float sA = r ? hu[1] : hu[0];
                float sB = r ? hu[2] : hu[1];
                float ra = __shfl_xor_sync(0xffffffffu, sA, 1);
                float rb = __shfl_xor_sync(0xffffffffu, sB, 1);
                h0v[0] = pack2(hu[0], hu[0]);
                h0v[1] = pack2(hu[1], hu[1]);
                h0v[2] = pack2(hu[2], hu[2]);
                h0v[3] = pack2(ra, ra);
                h0v[4] = pack2(rb, rb);
            }

            // ---- PIPELINE: layer-0 gate chains for step s+1 (independent of
            //      everything below; overlaps layer-1 chains + activations) ----
            u64 ga0n[6];
            l0_chains(ga0n, pack2(xn, xn));

            // ---- layer 1: 6 packed gate-pair chains (register weights) ----
            u64 ga1[6];
            #pragma unroll
            for (int p = 0; p < 6; ++p) {
                u64 a = w1[p][0];
                #pragma unroll
                for (int k = 0; k < HID_N; ++k)
                    a = fma2(w1[p][1 + k], h0v[k], a);
                #pragma unroll
                for (int k = 0; k < HID_N; ++k)
                    a = fma2(w1[p][6 + k], h1v[k], a);
                ga1[p] = a;
            }
            // ---- layer 1 activations ----
            #pragma unroll
            for (int q = 0; q < 3; ++q) {
                float iv, fv, gv, ov, ig, fg;
                unpack2(mul2(ga1[2 * q], HALF2), iv, fv);
                float ti = tanh_fast(iv), tf = tanh_fast(fv);
                unpack2(fma2(pack2(ti, tf), HALF2, HALF2), ig, fg);
                unpack2(ga1[2 * q + 1], gv, ov);
                float gg = tanh_fast(gv);
                float og = sig_fast(ov);
                float c = fmaf(fg, c1[q], ig * gg);
                c1[q] = c;
                hu[q] = og * tanh_fast(c);
            }
            // ---- folded head ----
            acc2 = fma2(pack2(hu[0], hu[1]), WfP[s], acc2);
            accS = fmaf(hu[2], WfS[s], accS);

            // ---- exchange h1 ----
            {
                float sA = r ? hu[1] : hu[0];
                float sB = r ? hu[2] : hu[1];
                float ra = __shfl_xor_sync(0xffffffffu, sA, 1);
                float rb = __shfl_xor_sync(0xffffffffu, sB, 1);
                h1v[0] = pack2(hu[0], hu[0]);
                h1v[1] = pack2(hu[1], hu[1]);
                h1v[2] = pack2(hu[2], hu[2]);
                h1v[3] = pack2(ra, ra);
                h1v[4] = pack2(rb, rb);
            }

            // rotate pipeline register
            #pragma unroll
            for (int p = 0; p < 6; ++p) ga0[p] = ga0n[p];
        }
        xq = xq_next;
    }

    // combine the two partial head sums; role 0 writes
    float alo, ahi;
    unpack2(acc2, alo, ahi);
    float part = accS + alo + ahi;
    float tot  = part + __shfl_xor_sync(0xffffffffu, part, 1);
    if (r == 0)
        out[e] = tot + g_beff;
}

// ---------------------------------------------------------------------------
// Harness entry. Inputs in metadata order:
// x, Wih0, Whh0, bih0, bhh0, Wih1, Whh1, bih1, bhh1, W1, b1, W2, b2
// ---------------------------------------------------------------------------
extern "C" void kernel_launch(void* const* d_in, const int* in_sizes, int n_in,
                              void* d_out, int out_size)
{
    const float* x    = (const float*)d_in[0];
    const float* Wih0 = (const float*)d_in[1];
    const float* Whh0 = (const float*)d_in[2];
    const float* bih0 = (const float*)d_in[3];
    const float* bhh0 = (const float*)d_in[4];
    const float* Wih1 = (const float*)d_in[5];
    const float* Whh1 = (const float*)d_in[6];
    const float* bih1 = (const float*)d_in[7];
    const float* bhh1 = (const float*)d_in[8];
    const float* W1   = (const float*)d_in[9];
    const float* b1   = (const float*)d_in[10];
    const float* W2   = (const float*)d_in[11];
    const float* b2   = (const float*)d_in[12];
    float* out = (float*)d_out;

    weff_kernel<<<(FLAT_N + 511) / 512, 512>>>(W1, b1, W2, b2);

    // 32768 threads: 2 per batch element, 256/block -> 128 blocks (2 warps/SMSP)
    lstm_fused_kernel<<<(BATCH_N * 2) / 256, 256>>>(x, Wih0, Whh0, bih0, bhh0,
                                                    Wih1, Whh1, bih1, bhh1, out);
}